// round 10
// baseline (speedup 1.0000x reference)
#include <cuda_runtime.h>
#include <cstdint>

// Resample2d (FlowNet2 bilinear warp), B=4, C=64, H=384, W=512.
//
// R9: smem tile, 8 channels per block (sync cost amortized, flow re-read kept
// off the L2 cap), 2-stage cp.async pipeline, cross-block latency hiding.
//   Block = 64x32 outputs, 512 threads, 4 px/thread.
//   Window = 44 rows x 80 cols, origin-clamped (shifted window) so the fill is
//   pure contiguous 16B cp.async. Taps outside the window use an exact global
//   fallback (P ~ 1e-9 for N(0,1) flow).
//   Grid = 8 x-tiles x 12 y-tiles x (4 batch * 8 channel-groups) = 3072 blocks.

static constexpr int B = 4;
static constexpr int C = 64;
static constexpr int H = 384;
static constexpr int W = 512;
static constexpr int HW = H * W;

static constexpr int TX = 64;
static constexpr int TY = 32;
static constexpr int HUP = 6;                  // halo rows above (nominal)
static constexpr int HL  = 8;                  // halo cols left (nominal)
static constexpr int TROWS = TY + 12;          // 44
static constexpr int TCOLS = TX + 16;          // 80
static constexpr int SST   = 84;               // smem row stride (floats)
static constexpr int SELEM = TROWS * SST;      // 3696 floats / stage
static constexpr int F4PROW = TCOLS / 4;       // 20
static constexpr int FILLU  = TROWS * F4PROW;  // 880 float4 units
static constexpr int NTHR = 512;
static constexpr int CPB  = 8;                 // channels per block

__device__ __forceinline__ int iclamp(int v, int lo, int hi) {
    return min(max(v, lo), hi);
}

__device__ __forceinline__ void cp_async16(uint32_t dst, const float* src) {
    asm volatile("cp.async.cg.shared.global [%0], [%1], 16;" :: "r"(dst), "l"(src));
}
__device__ __forceinline__ void cp_commit() {
    asm volatile("cp.async.commit_group;" ::: "memory");
}
template <int N>
__device__ __forceinline__ void cp_wait() {
    asm volatile("cp.async.wait_group %0;" :: "n"(N) : "memory");
}

__global__ __launch_bounds__(NTHR, 3) void resample2d_kernel(
    const float* __restrict__ in1,
    const float* __restrict__ flow,
    float* __restrict__ out)
{
    __shared__ float tile[2][SELEM];

    int tid = threadIdx.x;
    int xb = blockIdx.x * TX;
    int yb = blockIdx.y * TY;
    int bz = blockIdx.z >> 3;          // batch
    int c0 = (blockIdx.z & 7) * CPB;   // first channel of this block's group

    // Shifted (origin-clamped) window: fill stays contiguous & 16B aligned.
    int wxs = iclamp(xb - HL,  0, W - TCOLS);
    int wys = iclamp(yb - HUP, 0, H - TROWS);

    int x  = xb + (tid & 63);
    int ry = tid >> 6;                 // 0..7 (pixel p at row ry + 8p)

    // ---- fill precompute: 2 float4 units per thread ----
    int gsrc[2], soff[2];
    #pragma unroll
    for (int k = 0; k < 2; ++k) {
        int u = tid + k * NTHR;
        int r = u / F4PROW;
        int c4 = u - r * F4PROW;
        bool v = (u < FILLU);
        gsrc[k] = v ? ((wys + r) * W + wxs + c4 * 4) : 0;
        soff[k] = v ? (r * SST + c4 * 4) : -1;
    }
    uint32_t smbase = (uint32_t)__cvta_generic_to_shared(&tile[0][0]);

    // ---- per-pixel flow preamble (4 pixels per thread) ----
    float fa[4], fbw[4];
    unsigned pk0[4], pk1[4];
    int fbmask = 0;
    int opix0 = (yb + ry) * W + x;     // pixel p at opix0 + p*8*W

    const float* fptr = flow + (size_t)bz * 2 * HW;
    #pragma unroll
    for (int p = 0; p < 4; ++p) {
        int y   = yb + ry + 8 * p;
        int pix = y * W + x;
        float dx = fptr[pix];
        float dy = fptr[HW + pix];

        float xf = (float)x + dx;
        float yf = (float)y + dy;
        float x0f = floorf(xf);
        float y0f = floorf(yf);
        fa[p]  = xf - x0f;
        fbw[p] = yf - y0f;

        int x0i = (int)x0f;
        int y0i = (int)y0f;
        int x0 = iclamp(x0i,     0, W - 1);
        int x1 = iclamp(x0i + 1, 0, W - 1);
        int y0 = iclamp(y0i,     0, H - 1);
        int y1 = iclamp(y0i + 1, 0, H - 1);

        int tc0 = x0 - wxs;
        int tc1 = x1 - wxs;
        int tr0 = y0 - wys;
        int tr1 = y1 - wys;

        bool ok = (tc0 >= 0) & (tc1 < TCOLS) & (tr0 >= 0) & (tr1 < TROWS);
        if (ok) {
            pk0[p] = (unsigned)(tr0 * SST + tc0) | ((unsigned)(tr0 * SST + tc1) << 16);
            pk1[p] = (unsigned)(tr1 * SST + tc0) | ((unsigned)(tr1 * SST + tc1) << 16);
        } else {
            fbmask |= 1 << p;
            pk0[p] = (unsigned)(y0 * W + x0);
            pk1[p] = (unsigned)(x1 - x0) | ((unsigned)(y1 - y0) << 1);
        }
    }

    const float* bin  = in1 + (size_t)bz * C * HW + (size_t)c0 * HW;
    float*       bout = out + (size_t)bz * C * HW + (size_t)c0 * HW;

    // ---- prologue: fill channel 0 into stage 0 ----
    {
        #pragma unroll
        for (int k = 0; k < 2; ++k)
            if (soff[k] >= 0) cp_async16(smbase + soff[k] * 4, bin + gsrc[k]);
        cp_commit();
    }

    for (int c = 0; c < CPB; ++c) {
        if (c + 1 < CPB) {
            const float* nsrc = bin + (size_t)(c + 1) * HW;
            uint32_t db = smbase + (uint32_t)(((c + 1) & 1) * SELEM * 4);
            #pragma unroll
            for (int k = 0; k < 2; ++k)
                if (soff[k] >= 0) cp_async16(db + soff[k] * 4, nsrc + gsrc[k]);
            cp_commit();
            cp_wait<1>();      // fill for channel c has landed
        } else {
            cp_wait<0>();
        }
        __syncthreads();

        const float* tl  = tile[c & 1];
        const float* src = bin + (size_t)c * HW;
        float*       dst = bout + (size_t)c * HW;

        #pragma unroll
        for (int p = 0; p < 4; ++p) {
            float a  = fa[p];
            float bw = fbw[p];
            float w00 = (1.0f - a) * (1.0f - bw);
            float w10 = a * (1.0f - bw);
            float w01 = (1.0f - a) * bw;
            float w11 = a * bw;

            float res;
            if (!((fbmask >> p) & 1)) {
                int t00 = pk0[p] & 0xffff;
                int t10 = pk0[p] >> 16;
                int t01 = pk1[p] & 0xffff;
                int t11 = pk1[p] >> 16;
                res = w00 * tl[t00] + w10 * tl[t10]
                    + w01 * tl[t01] + w11 * tl[t11];
            } else {
                int g00 = (int)pk0[p];
                int dxi = pk1[p] & 1;
                int dyi = (pk1[p] >> 1) & 1;
                const float* gp = src + g00;
                res = w00 * __ldg(gp)
                    + w10 * __ldg(gp + dxi)
                    + w01 * __ldg(gp + dyi * W)
                    + w11 * __ldg(gp + dyi * W + dxi);
            }
            dst[opix0 + p * 8 * W] = res;
        }
        __syncthreads();       // all reads of stage c&1 done before its refill
    }
}

extern "C" void kernel_launch(void* const* d_in, const int* in_sizes, int n_in,
                              void* d_out, int out_size)
{
    const float* in1  = (const float*)d_in[0];
    const float* flow = (const float*)d_in[1];
    float*       out  = (float*)d_out;

    dim3 grid(W / TX, H / TY, B * (C / CPB));   // 8 x 12 x 32 = 3072 blocks
    resample2d_kernel<<<grid, NTHR>>>(in1, flow, out);
}